// round 3
// baseline (speedup 1.0000x reference)
#include <cuda_runtime.h>
#include <cuda_fp16.h>
#include <math.h>

#define NN 100000
#define IN_CH 16
#define HID 128
#define EE 1600000
#define ET (EE + NN)
#define NB 98            // ceil(NN/1024)
#define NEG 0.2f
#define LN_EPS 1e-5f

// ---------------- scratch (static device globals; zero-init at load) ------------
__device__ __half g_h1h[NN * HID];    // layer1 features (fp16, gather target)
__device__ __half g_h2h[NN * HID];    // layer2 features (fp16, gather target)
__device__ __half g_hlnh[NN * HID];   // post ELU+LN features (fp16, gemm2 A input)
__device__ float  g_as1[NN * 4];
__device__ float  g_ad1[NN * 4];
__device__ float  g_as2[NN];
__device__ float  g_ad2[NN];
__device__ int    g_deg[NN];          // zeroed by agg2 tail of previous run
__device__ int    g_flagged[NB];      // scan lookback flags; zeroed by agg2 tail
__device__ int    g_rowptr[NN + 1];
__device__ int    g_cursor[NN];
__device__ int    g_esrc[ET];

__device__ __forceinline__ float lrelu(float e) { return e > 0.f ? e : NEG * e; }

// ---------------- mma / ldmatrix helpers ---------------------------------------
__device__ __forceinline__ void mma16816(float& d0, float& d1, float& d2, float& d3,
                                         unsigned a0, unsigned a1, unsigned a2, unsigned a3,
                                         unsigned b0, unsigned b1) {
    asm volatile(
        "mma.sync.aligned.m16n8k16.row.col.f32.f16.f16.f32 "
        "{%0,%1,%2,%3},{%4,%5,%6,%7},{%8,%9},{%0,%1,%2,%3};"
        : "+f"(d0), "+f"(d1), "+f"(d2), "+f"(d3)
        : "r"(a0), "r"(a1), "r"(a2), "r"(a3), "r"(b0), "r"(b1));
}
__device__ __forceinline__ void ldsm4(unsigned& r0, unsigned& r1, unsigned& r2, unsigned& r3,
                                      unsigned addr) {
    asm volatile("ldmatrix.sync.aligned.m8n8.x4.shared.b16 {%0,%1,%2,%3},[%4];"
                 : "=r"(r0), "=r"(r1), "=r"(r2), "=r"(r3) : "r"(addr));
}
__device__ __forceinline__ void ldsm4t(unsigned& r0, unsigned& r1, unsigned& r2, unsigned& r3,
                                       unsigned addr) {
    asm volatile("ldmatrix.sync.aligned.m8n8.x4.trans.shared.b16 {%0,%1,%2,%3},[%4];"
                 : "=r"(r0), "=r"(r1), "=r"(r2), "=r"(r3) : "r"(addr));
}

// ---------------- K0: gemm1 (16 nodes/block) + alpha dots + degree histogram ----
__global__ void __launch_bounds__(128) k_gemm1h(const float* __restrict__ x,
                                                const float* __restrict__ W1,
                                                const float* __restrict__ a_src,
                                                const float* __restrict__ a_dst,
                                                const int* __restrict__ ei) {
    __shared__ float sW1[IN_CH * HID];   // 2048
    __shared__ float spa[IN_CH * 8];     // pa[k][h][sd]
    __shared__ float sx[16 * IN_CH];     // 16 nodes of x
    int t = threadIdx.x;
    int n0 = blockIdx.x * 16;

#pragma unroll
    for (int i = 0; i < 16; i++) sW1[i * 128 + t] = W1[i * 128 + t];
    __syncthreads();
    {   // pa[k*8 + h*2 + sd] = sum_c W1[k, h*32+c] * a_{sd}[h*32+c]
        int k = t >> 3, h = (t >> 1) & 3, sd = t & 1;
        const float* av = sd ? a_dst : a_src;
        float s = 0.f;
#pragma unroll
        for (int c = 0; c < 32; c++) s = fmaf(sW1[k * 128 + h * 32 + c], av[h * 32 + c], s);
        spa[t] = s;
    }
    if (t < 64) ((float4*)sx)[t] = ((const float4*)x)[n0 * 4 + t];
    __syncthreads();

#pragma unroll 2
    for (int i = 0; i < 16; i++) {
        const float* xr = &sx[i * IN_CH];
        float acc = 0.f;
#pragma unroll
        for (int k = 0; k < IN_CH; k++) acc = fmaf(xr[k], sW1[k * 128 + t], acc);
        g_h1h[(n0 + i) * HID + t] = __float2half_rn(acc);
        if (t < 8) {
            int h = t & 3, sd = t >> 2;
            float v = 0.f;
#pragma unroll
            for (int k = 0; k < IN_CH; k++) v = fmaf(xr[k], spa[k * 8 + h * 2 + sd], v);
            if (sd == 0) g_as1[(n0 + i) * 4 + h] = v;
            else         g_ad1[(n0 + i) * 4 + h] = v;
        }
    }

    // degree histogram (grid-stride over all edges incl. self loops)
    for (int e = blockIdx.x * 128 + t; e < ET; e += 6250 * 128) {
        int d = (e < EE) ? ei[EE + e] : (e - EE);
        atomicAdd(&g_deg[d], 1);
    }
}

// ---------------- K1: single-kernel scan (chained lookback) ---------------------
__global__ void __launch_bounds__(1024) k_scan() {
    __shared__ int sh[1024];
    __shared__ int s_prefix;
    int t = threadIdx.x, bid = blockIdx.x;
    int i = bid * 1024 + t;
    int v = (i < NN) ? g_deg[i] : 0;
    sh[t] = v;
    __syncthreads();
#pragma unroll
    for (int off = 1; off < 1024; off <<= 1) {
        int tv = (t >= off) ? sh[t - off] : 0;
        __syncthreads();
        sh[t] += tv;
        __syncthreads();
    }
    if (t == 0) {
        int p = 0;
        if (bid > 0) {
            volatile int* f = &g_flagged[bid - 1];
            int x;
            do { x = *f; } while (x == 0);
            p = x - 1;
        }
        *(volatile int*)&g_flagged[bid] = p + sh[1023] + 1;  // publish inclusive total
        s_prefix = p;
    }
    __syncthreads();
    if (i < NN) {
        int r = s_prefix + sh[t] - v;
        g_rowptr[i] = r;
        g_cursor[i] = r;
    }
    if (bid == NB - 1 && t == 0) g_rowptr[NN] = ET;
}

// ---------------- K2: scatter edges into CSR buckets ---------------------------
__global__ void k_scatter(const int* __restrict__ ei) {
    int e = blockIdx.x * blockDim.x + threadIdx.x;
    if (e < ET) {
        int s, d;
        if (e < EE) { s = ei[e]; d = ei[EE + e]; }
        else        { s = e - EE; d = s; }
        int p = atomicAdd(&g_cursor[d], 1);
        g_esrc[p] = s;
    }
}

// ---------------- K3: layer-1 GAT agg (single pass) + bias + ELU + LN -----------
__global__ void __launch_bounds__(256) k_agg1(const float* __restrict__ b1,
                                              const float* __restrict__ g1,
                                              const float* __restrict__ bt1) {
    int n = blockIdx.x * 8 + (threadIdx.x >> 5);
    int lane = threadIdx.x & 31;
    int h = lane >> 3;
    float adh = g_ad1[n * 4 + h];
    int start = g_rowptr[n], end = g_rowptr[n + 1];

    float den = 0.f;
    float a0 = 0.f, a1 = 0.f, a2 = 0.f, a3 = 0.f;
#pragma unroll 4
    for (int j = start; j < end; j++) {
        int s = g_esrc[j];
        float as = __ldg(&g_as1[s * 4 + h]);
        float w = __expf(lrelu(as + adh));
        den += w;
        float2 raw = *(const float2*)&g_h1h[s * HID + lane * 4];
        __half2 p01 = *(__half2*)&raw.x;
        __half2 p23 = *(__half2*)&raw.y;
        float2 f01 = __half22float2(p01);
        float2 f23 = __half22float2(p23);
        a0 = fmaf(w, f01.x, a0);
        a1 = fmaf(w, f01.y, a1);
        a2 = fmaf(w, f23.x, a2);
        a3 = fmaf(w, f23.y, a3);
    }
    float rd = 1.0f / den;
    a0 *= rd; a1 *= rd; a2 *= rd; a3 *= rd;

    int ch = lane * 4;
    a0 += b1[ch]; a1 += b1[ch + 1]; a2 += b1[ch + 2]; a3 += b1[ch + 3];
    a0 = a0 > 0.f ? a0 : expm1f(a0);
    a1 = a1 > 0.f ? a1 : expm1f(a1);
    a2 = a2 > 0.f ? a2 : expm1f(a2);
    a3 = a3 > 0.f ? a3 : expm1f(a3);
    float s4 = a0 + a1 + a2 + a3;
#pragma unroll
    for (int off = 16; off; off >>= 1) s4 += __shfl_xor_sync(0xffffffffu, s4, off);
    float mu = s4 * (1.0f / 128.0f);
    float c0 = a0 - mu, c1 = a1 - mu, c2 = a2 - mu, c3 = a3 - mu;
    float v4 = c0 * c0 + c1 * c1 + c2 * c2 + c3 * c3;
#pragma unroll
    for (int off = 16; off; off >>= 1) v4 += __shfl_xor_sync(0xffffffffu, v4, off);
    float inv = rsqrtf(v4 * (1.0f / 128.0f) + LN_EPS);
    float o0 = fmaf(c0 * inv, g1[ch + 0], bt1[ch + 0]);
    float o1 = fmaf(c1 * inv, g1[ch + 1], bt1[ch + 1]);
    float o2 = fmaf(c2 * inv, g1[ch + 2], bt1[ch + 2]);
    float o3 = fmaf(c3 * inv, g1[ch + 3], bt1[ch + 3]);
    __half2 p01 = __floats2half2_rn(o0, o1);
    __half2 p23 = __floats2half2_rn(o2, o3);
    uint2 st;
    st.x = *(unsigned*)&p01;
    st.y = *(unsigned*)&p23;
    *(uint2*)&g_hlnh[n * HID + ch] = st;
}

// ---------------- K4: h2 = hln @ W2 via fp16 tensor cores (+ alpha2 dots) -------
#define APITCH 136   // halves; 272B row pitch (smem swizzle-free via pad)
__global__ void __launch_bounds__(128) k_gemm2t(const float* __restrict__ W2,
                                                const float* __restrict__ asw,
                                                const float* __restrict__ adw) {
    extern __shared__ __half smh[];
    __half* sW = smh;                    // [128][APITCH]
    __half* sA = smh + 128 * APITCH;     // [32][APITCH], reused as C staging
    int t = threadIdx.x;
    int w = t >> 5, lane = t & 31;
    int mrow0 = (w & 1) * 16;
    int ncol0 = (w >> 1) * 64;

    for (int i = t; i < 16384; i += 128) {
        int r = i >> 7, c = i & 127;
        sW[r * APITCH + c] = __float2half_rn(W2[i]);
    }
    unsigned swb = (unsigned)__cvta_generic_to_shared(sW);
    unsigned sab = (unsigned)__cvta_generic_to_shared(sA);
    // ldmatrix lane addresses (constant per lane)
    unsigned a_off = ((unsigned)(lane & 15) * APITCH + ((lane >> 4) << 3)) * 2;
    __syncthreads();

    for (int n0 = blockIdx.x * 32; n0 < NN; n0 += 592 * 32) {
        __syncthreads();  // protect C staging of previous tile
        // stage A: 32 rows x 128 halves
        for (int i = t; i < 32 * 64; i += 128) {
            int r = i >> 6, c2 = i & 63;
            ((unsigned*)sA)[r * (APITCH / 2) + c2] =
                ((const unsigned*)&g_hlnh[(unsigned)(n0 + r) * HID])[c2];
        }
        __syncthreads();

        float acc[8][4];
#pragma unroll
        for (int q = 0; q < 8; q++)
#pragma unroll
            for (int r = 0; r < 4; r++) acc[q][r] = 0.f;

#pragma unroll
        for (int k0 = 0; k0 < 8; k0++) {
            unsigned a0, a1, a2, a3;
            ldsm4(a0, a1, a2, a3, sab + (unsigned)mrow0 * APITCH * 2 + (unsigned)k0 * 32 + a_off);
#pragma unroll
            for (int nt = 0; nt < 4; nt++) {
                unsigned b0, b1, b2, b3;
                unsigned baddr = swb + ((unsigned)(k0 * 16 + (lane & 15)) * APITCH
                                        + ncol0 + nt * 16 + ((lane >> 4) << 3)) * 2;
                ldsm4t(b0, b1, b2, b3, baddr);
                mma16816(acc[2 * nt][0], acc[2 * nt][1], acc[2 * nt][2], acc[2 * nt][3],
                         a0, a1, a2, a3, b0, b1);
                mma16816(acc[2 * nt + 1][0], acc[2 * nt + 1][1], acc[2 * nt + 1][2], acc[2 * nt + 1][3],
                         a0, a1, a2, a3, b2, b3);
            }
        }
        __syncthreads();  // done reading sA/sW for this tile

        // stage C (fp16) into sA
#pragma unroll
        for (int nt = 0; nt < 8; nt++) {
            int n = ncol0 + nt * 8 + 2 * (lane & 3);
            int r = mrow0 + (lane >> 2);
            __half2 lo = __floats2half2_rn(acc[nt][0], acc[nt][1]);
            __half2 hi = __floats2half2_rn(acc[nt][2], acc[nt][3]);
            *(__half2*)&sA[r * APITCH + n] = lo;
            *(__half2*)&sA[(r + 8) * APITCH + n] = hi;
        }
        __syncthreads();

        // write h2 to global (coalesced) + alpha2 dots
        for (int i = t; i < 32 * 64; i += 128) {
            int r = i >> 6, c2 = i & 63;
            ((unsigned*)&g_h2h[(unsigned)(n0 + r) * HID])[c2] =
                ((unsigned*)sA)[r * (APITCH / 2) + c2];
        }
        if (t < 32) {
            float ps = 0.f, pd = 0.f;
#pragma unroll 4
            for (int c = 0; c < 128; c += 2) {
                float2 f = __half22float2(*(__half2*)&sA[t * APITCH + c]);
                ps = fmaf(f.x, __ldg(&asw[c]), fmaf(f.y, __ldg(&asw[c + 1]), ps));
                pd = fmaf(f.x, __ldg(&adw[c]), fmaf(f.y, __ldg(&adw[c + 1]), pd));
            }
            g_as2[n0 + t] = ps;
            g_ad2[n0 + t] = pd;
        }
    }
}

// ---------------- K5: layer-2 GAT agg + bias + ELU + LN -> out, + re-zero -------
__global__ void __launch_bounds__(256) k_agg2(const float* __restrict__ b2,
                                              const float* __restrict__ g2,
                                              const float* __restrict__ bt2,
                                              float* __restrict__ out) {
    int n = blockIdx.x * 8 + (threadIdx.x >> 5);
    int lane = threadIdx.x & 31;
    float adn = g_ad2[n];
    int start = g_rowptr[n], end = g_rowptr[n + 1];

    float den = 0.f;
    float a0 = 0.f, a1 = 0.f, a2 = 0.f, a3 = 0.f;
#pragma unroll 4
    for (int j = start; j < end; j++) {
        int s = g_esrc[j];
        float as = __ldg(&g_as2[s]);
        float w = __expf(lrelu(as + adn));
        den += w;
        float2 raw = *(const float2*)&g_h2h[s * HID + lane * 4];
        __half2 p01 = *(__half2*)&raw.x;
        __half2 p23 = *(__half2*)&raw.y;
        float2 f01 = __half22float2(p01);
        float2 f23 = __half22float2(p23);
        a0 = fmaf(w, f01.x, a0);
        a1 = fmaf(w, f01.y, a1);
        a2 = fmaf(w, f23.x, a2);
        a3 = fmaf(w, f23.y, a3);
    }
    float rd = 1.0f / den;
    a0 *= rd; a1 *= rd; a2 *= rd; a3 *= rd;

    int ch = lane * 4;
    a0 += b2[ch]; a1 += b2[ch + 1]; a2 += b2[ch + 2]; a3 += b2[ch + 3];
    a0 = a0 > 0.f ? a0 : expm1f(a0);
    a1 = a1 > 0.f ? a1 : expm1f(a1);
    a2 = a2 > 0.f ? a2 : expm1f(a2);
    a3 = a3 > 0.f ? a3 : expm1f(a3);
    float s4 = a0 + a1 + a2 + a3;
#pragma unroll
    for (int off = 16; off; off >>= 1) s4 += __shfl_xor_sync(0xffffffffu, s4, off);
    float mu = s4 * (1.0f / 128.0f);
    float c0 = a0 - mu, c1 = a1 - mu, c2 = a2 - mu, c3 = a3 - mu;
    float v4 = c0 * c0 + c1 * c1 + c2 * c2 + c3 * c3;
#pragma unroll
    for (int off = 16; off; off >>= 1) v4 += __shfl_xor_sync(0xffffffffu, v4, off);
    float inv = rsqrtf(v4 * (1.0f / 128.0f) + LN_EPS);
    float4 o;
    o.x = fmaf(c0 * inv, g2[ch + 0], bt2[ch + 0]);
    o.y = fmaf(c1 * inv, g2[ch + 1], bt2[ch + 1]);
    o.z = fmaf(c2 * inv, g2[ch + 2], bt2[ch + 2]);
    o.w = fmaf(c3 * inv, g2[ch + 3], bt2[ch + 3]);
    *(float4*)&out[n * HID + ch] = o;

    // re-zero scratch for next graph replay (statics are zero-init for run #1)
    int gi = blockIdx.x * 256 + threadIdx.x;
    if (gi < NN) g_deg[gi] = 0;
    if (gi < NB) g_flagged[gi] = 0;
}

// ---------------- launch ----------------
extern "C" void kernel_launch(void* const* d_in, const int* in_sizes, int n_in,
                              void* d_out, int out_size) {
    const float* x     = (const float*)d_in[0];
    const int*   ei    = (const int*)d_in[1];
    const float* W1    = (const float*)d_in[2];
    const float* asr1  = (const float*)d_in[3];
    const float* adt1  = (const float*)d_in[4];
    const float* b1    = (const float*)d_in[5];
    const float* g1    = (const float*)d_in[6];
    const float* bt1   = (const float*)d_in[7];
    const float* W2    = (const float*)d_in[8];
    const float* asr2  = (const float*)d_in[9];
    const float* adt2  = (const float*)d_in[10];
    const float* b2    = (const float*)d_in[11];
    const float* g2    = (const float*)d_in[12];
    const float* bt2   = (const float*)d_in[13];
    float* out = (float*)d_out;

    const int SMEM2 = (128 * APITCH + 32 * APITCH) * sizeof(__half);  // 43.5KB
    cudaFuncSetAttribute(k_gemm2t, cudaFuncAttributeMaxDynamicSharedMemorySize, SMEM2);

    k_gemm1h<<<6250, 128>>>(x, W1, asr1, adt1, ei);
    k_scan<<<NB, 1024>>>();
    k_scatter<<<(ET + 255) / 256, 256>>>(ei);
    k_agg1<<<NN / 8, 256>>>(b1, g1, bt1);
    k_gemm2t<<<592, 128, SMEM2>>>(W2, asr2, adt2);
    k_agg2<<<NN / 8, 256>>>(b2, g2, bt2, out);
}

// round 4
// speedup vs baseline: 1.5979x; 1.5979x over previous
#include <cuda_runtime.h>
#include <cuda_fp16.h>
#include <math.h>

#define NN 100000
#define IN_CH 16
#define HID 128
#define EE 1600000
#define ET (EE + NN)
#define NB 98            // ceil(NN/1024)
#define NEG 0.2f
#define LN_EPS 1e-5f

// ---------------- scratch (static device globals; zero-init at load) ------------
__device__ __half g_h1h[NN * HID];    // layer1 features (fp16, gather target)
__device__ __half g_h2h[NN * HID];    // layer2 features (fp16, gather target)
__device__ __half g_hlnh[NN * HID];   // post ELU+LN features (fp16, gemm2 A input)
__device__ float  g_as1[NN * 4];
__device__ float  g_ad1[NN * 4];
__device__ float  g_as2[NN];
__device__ float  g_ad2[NN];
__device__ float  g_w1[ET * 4];       // layer-1 per-edge softmax numerators (CSR order)
__device__ float  g_w2[ET];           // layer-2 per-edge softmax numerators (CSR order)
__device__ int    g_deg[NN];          // zeroed by agg2 tail of previous run
__device__ int    g_scanpart[NN];
__device__ int    g_blocksum[NB];
__device__ int    g_rowptr[NN + 1];
__device__ int    g_cursor[NN];
__device__ int    g_esrc[ET];
__device__ int    g_edst[ET];

__device__ __forceinline__ float lrelu(float e) { return e > 0.f ? e : NEG * e; }

// ---------------- mma / ldmatrix helpers ---------------------------------------
__device__ __forceinline__ void mma16816(float& d0, float& d1, float& d2, float& d3,
                                         unsigned a0, unsigned a1, unsigned a2, unsigned a3,
                                         unsigned b0, unsigned b1) {
    asm volatile(
        "mma.sync.aligned.m16n8k16.row.col.f32.f16.f16.f32 "
        "{%0,%1,%2,%3},{%4,%5,%6,%7},{%8,%9},{%0,%1,%2,%3};"
        : "+f"(d0), "+f"(d1), "+f"(d2), "+f"(d3)
        : "r"(a0), "r"(a1), "r"(a2), "r"(a3), "r"(b0), "r"(b1));
}
__device__ __forceinline__ void ldsm4(unsigned& r0, unsigned& r1, unsigned& r2, unsigned& r3,
                                      unsigned addr) {
    asm volatile("ldmatrix.sync.aligned.m8n8.x4.shared.b16 {%0,%1,%2,%3},[%4];"
                 : "=r"(r0), "=r"(r1), "=r"(r2), "=r"(r3) : "r"(addr));
}
__device__ __forceinline__ void ldsm4t(unsigned& r0, unsigned& r1, unsigned& r2, unsigned& r3,
                                       unsigned addr) {
    asm volatile("ldmatrix.sync.aligned.m8n8.x4.trans.shared.b16 {%0,%1,%2,%3},[%4];"
                 : "=r"(r0), "=r"(r1), "=r"(r2), "=r"(r3) : "r"(addr));
}

// ---------------- K0: gemm1 (16 nodes/block) + alpha dots + degree histogram ----
__global__ void __launch_bounds__(128) k_gemm1h(const float* __restrict__ x,
                                                const float* __restrict__ W1,
                                                const float* __restrict__ a_src,
                                                const float* __restrict__ a_dst,
                                                const int* __restrict__ ei) {
    __shared__ float sW1[IN_CH * HID];   // 2048
    __shared__ float spa[IN_CH * 8];     // pa[k][h][sd]
    __shared__ float sx[16 * IN_CH];     // 16 nodes of x
    int t = threadIdx.x;
    int n0 = blockIdx.x * 16;

#pragma unroll
    for (int i = 0; i < 16; i++) sW1[i * 128 + t] = W1[i * 128 + t];
    __syncthreads();
    {   // pa[k*8 + h*2 + sd] = sum_c W1[k, h*32+c] * a_{sd}[h*32+c]
        int k = t >> 3, h = (t >> 1) & 3, sd = t & 1;
        const float* av = sd ? a_dst : a_src;
        float s = 0.f;
#pragma unroll
        for (int c = 0; c < 32; c++) s = fmaf(sW1[k * 128 + h * 32 + c], av[h * 32 + c], s);
        spa[t] = s;
    }
    if (t < 64) ((float4*)sx)[t] = ((const float4*)x)[n0 * 4 + t];
    __syncthreads();

#pragma unroll 2
    for (int i = 0; i < 16; i++) {
        const float* xr = &sx[i * IN_CH];
        float acc = 0.f;
#pragma unroll
        for (int k = 0; k < IN_CH; k++) acc = fmaf(xr[k], sW1[k * 128 + t], acc);
        g_h1h[(n0 + i) * HID + t] = __float2half_rn(acc);
        if (t < 8) {
            int h = t & 3, sd = t >> 2;
            float v = 0.f;
#pragma unroll
            for (int k = 0; k < IN_CH; k++) v = fmaf(xr[k], spa[k * 8 + h * 2 + sd], v);
            if (sd == 0) g_as1[(n0 + i) * 4 + h] = v;
            else         g_ad1[(n0 + i) * 4 + h] = v;
        }
    }

    // degree histogram (grid-stride over all edges incl. self loops)
    for (int e = blockIdx.x * 128 + t; e < ET; e += 6250 * 128) {
        int d = (e < EE) ? ei[EE + e] : (e - EE);
        atomicAdd(&g_deg[d], 1);
    }
}

// ---------------- K1/K2: two-phase scan (proven fast path) ----------------------
__global__ void __launch_bounds__(1024) k_scan1() {
    __shared__ int sh[1024];
    int t = threadIdx.x;
    int i = blockIdx.x * 1024 + t;
    int v = (i < NN) ? g_deg[i] : 0;
    sh[t] = v;
    __syncthreads();
#pragma unroll
    for (int off = 1; off < 1024; off <<= 1) {
        int tv = (t >= off) ? sh[t - off] : 0;
        __syncthreads();
        sh[t] += tv;
        __syncthreads();
    }
    if (i < NN) g_scanpart[i] = sh[t] - v;  // exclusive within block
    if (t == 1023) g_blocksum[blockIdx.x] = sh[1023];
}

__global__ void __launch_bounds__(1024) k_scan2() {
    __shared__ int soff;
    int t = threadIdx.x;
    if (t == 0) {
        int s = 0;
        for (int b = 0; b < blockIdx.x; b++) s += g_blocksum[b];
        soff = s;
    }
    __syncthreads();
    int i = blockIdx.x * 1024 + t;
    if (i < NN) {
        int r = g_scanpart[i] + soff;
        g_rowptr[i] = r;
        g_cursor[i] = r;
    }
    if (i == 0) g_rowptr[NN] = ET;
}

// ---------------- K3: scatter edges + layer-1 edge weights ---------------------
__global__ void k_scatterW(const int* __restrict__ ei) {
    int e = blockIdx.x * blockDim.x + threadIdx.x;
    if (e >= ET) return;
    int s, d;
    if (e < EE) { s = ei[e]; d = ei[EE + e]; }
    else        { s = e - EE; d = s; }
    int p = atomicAdd(&g_cursor[d], 1);
    g_esrc[p] = s;
    g_edst[p] = d;
    float4 as = *(const float4*)&g_as1[s * 4];
    float4 ad = *(const float4*)&g_ad1[d * 4];
    float4 w;
    w.x = __expf(lrelu(as.x + ad.x));
    w.y = __expf(lrelu(as.y + ad.y));
    w.z = __expf(lrelu(as.z + ad.z));
    w.w = __expf(lrelu(as.w + ad.w));
    *(float4*)&g_w1[p * 4] = w;
}

// ---------------- K4: layer-1 GAT agg (precomputed weights) + ELU + LN ----------
__global__ void __launch_bounds__(256) k_agg1(const float* __restrict__ b1,
                                              const float* __restrict__ g1,
                                              const float* __restrict__ bt1) {
    int n = blockIdx.x * 8 + (threadIdx.x >> 5);
    int lane = threadIdx.x & 31;
    int h = lane >> 3;
    int start = g_rowptr[n], end = g_rowptr[n + 1];

    float den = 0.f;
    float a0 = 0.f, a1 = 0.f, a2 = 0.f, a3 = 0.f;
#pragma unroll 4
    for (int j = start; j < end; j++) {
        int s = __ldg(&g_esrc[j]);
        float wf = __ldg(&g_w1[j * 4 + h]);
        den += wf;
        uint2 raw = *(const uint2*)&g_h1h[s * HID + lane * 4];
        float2 f01 = __half22float2(*(__half2*)&raw.x);
        float2 f23 = __half22float2(*(__half2*)&raw.y);
        a0 = fmaf(wf, f01.x, a0);
        a1 = fmaf(wf, f01.y, a1);
        a2 = fmaf(wf, f23.x, a2);
        a3 = fmaf(wf, f23.y, a3);
    }
    float rd = 1.0f / den;
    a0 *= rd; a1 *= rd; a2 *= rd; a3 *= rd;

    int ch = lane * 4;
    a0 += b1[ch]; a1 += b1[ch + 1]; a2 += b1[ch + 2]; a3 += b1[ch + 3];
    a0 = a0 > 0.f ? a0 : expm1f(a0);
    a1 = a1 > 0.f ? a1 : expm1f(a1);
    a2 = a2 > 0.f ? a2 : expm1f(a2);
    a3 = a3 > 0.f ? a3 : expm1f(a3);
    float s4 = a0 + a1 + a2 + a3;
#pragma unroll
    for (int off = 16; off; off >>= 1) s4 += __shfl_xor_sync(0xffffffffu, s4, off);
    float mu = s4 * (1.0f / 128.0f);
    float c0 = a0 - mu, c1 = a1 - mu, c2 = a2 - mu, c3 = a3 - mu;
    float v4 = c0 * c0 + c1 * c1 + c2 * c2 + c3 * c3;
#pragma unroll
    for (int off = 16; off; off >>= 1) v4 += __shfl_xor_sync(0xffffffffu, v4, off);
    float inv = rsqrtf(v4 * (1.0f / 128.0f) + LN_EPS);
    float o0 = fmaf(c0 * inv, g1[ch + 0], bt1[ch + 0]);
    float o1 = fmaf(c1 * inv, g1[ch + 1], bt1[ch + 1]);
    float o2 = fmaf(c2 * inv, g1[ch + 2], bt1[ch + 2]);
    float o3 = fmaf(c3 * inv, g1[ch + 3], bt1[ch + 3]);
    __half2 p01 = __floats2half2_rn(o0, o1);
    __half2 p23 = __floats2half2_rn(o2, o3);
    uint2 st;
    st.x = *(unsigned*)&p01;
    st.y = *(unsigned*)&p23;
    *(uint2*)&g_hlnh[n * HID + ch] = st;
}

// ---------------- K5: h2 = hln @ W2 via fp16 tensor cores (+ alpha2 dots) -------
#define APITCH 136   // halves; 272B row pitch
__global__ void __launch_bounds__(128) k_gemm2t(const float* __restrict__ W2,
                                                const float* __restrict__ asw,
                                                const float* __restrict__ adw) {
    extern __shared__ __half smh[];
    __half* sW = smh;                    // [128][APITCH]
    __half* sA = smh + 128 * APITCH;     // [32][APITCH], reused as C staging
    int t = threadIdx.x;
    int w = t >> 5, lane = t & 31;
    int mrow0 = (w & 1) * 16;
    int ncol0 = (w >> 1) * 64;

    for (int i = t; i < 16384; i += 128) {
        int r = i >> 7, c = i & 127;
        sW[r * APITCH + c] = __float2half_rn(W2[i]);
    }
    unsigned swb = (unsigned)__cvta_generic_to_shared(sW);
    unsigned sab = (unsigned)__cvta_generic_to_shared(sA);
    unsigned a_off = ((unsigned)(lane & 15) * APITCH + ((lane >> 4) << 3)) * 2;
    __syncthreads();

    for (int n0 = blockIdx.x * 32; n0 < NN; n0 += 592 * 32) {
        __syncthreads();
        for (int i = t; i < 32 * 64; i += 128) {
            int r = i >> 6, c2 = i & 63;
            ((unsigned*)sA)[r * (APITCH / 2) + c2] =
                ((const unsigned*)&g_hlnh[(unsigned)(n0 + r) * HID])[c2];
        }
        __syncthreads();

        float acc[8][4];
#pragma unroll
        for (int q = 0; q < 8; q++)
#pragma unroll
            for (int r = 0; r < 4; r++) acc[q][r] = 0.f;

#pragma unroll
        for (int k0 = 0; k0 < 8; k0++) {
            unsigned a0, a1, a2, a3;
            ldsm4(a0, a1, a2, a3, sab + (unsigned)mrow0 * APITCH * 2 + (unsigned)k0 * 32 + a_off);
#pragma unroll
            for (int nt = 0; nt < 4; nt++) {
                unsigned b0, b1, b2, b3;
                unsigned baddr = swb + ((unsigned)(k0 * 16 + (lane & 15)) * APITCH
                                        + ncol0 + nt * 16 + ((lane >> 4) << 3)) * 2;
                ldsm4t(b0, b1, b2, b3, baddr);
                mma16816(acc[2 * nt][0], acc[2 * nt][1], acc[2 * nt][2], acc[2 * nt][3],
                         a0, a1, a2, a3, b0, b1);
                mma16816(acc[2 * nt + 1][0], acc[2 * nt + 1][1], acc[2 * nt + 1][2], acc[2 * nt + 1][3],
                         a0, a1, a2, a3, b2, b3);
            }
        }
        __syncthreads();

#pragma unroll
        for (int nt = 0; nt < 8; nt++) {
            int n = ncol0 + nt * 8 + 2 * (lane & 3);
            int r = mrow0 + (lane >> 2);
            __half2 lo = __floats2half2_rn(acc[nt][0], acc[nt][1]);
            __half2 hi = __floats2half2_rn(acc[nt][2], acc[nt][3]);
            *(__half2*)&sA[r * APITCH + n] = lo;
            *(__half2*)&sA[(r + 8) * APITCH + n] = hi;
        }
        __syncthreads();

        for (int i = t; i < 32 * 64; i += 128) {
            int r = i >> 6, c2 = i & 63;
            ((unsigned*)&g_h2h[(unsigned)(n0 + r) * HID])[c2] =
                ((unsigned*)sA)[r * (APITCH / 2) + c2];
        }
        if (t < 32) {
            float ps = 0.f, pd = 0.f;
#pragma unroll 4
            for (int c = 0; c < 128; c += 2) {
                float2 f = __half22float2(*(__half2*)&sA[t * APITCH + c]);
                ps = fmaf(f.x, __ldg(&asw[c]), fmaf(f.y, __ldg(&asw[c + 1]), ps));
                pd = fmaf(f.x, __ldg(&adw[c]), fmaf(f.y, __ldg(&adw[c + 1]), pd));
            }
            g_as2[n0 + t] = ps;
            g_ad2[n0 + t] = pd;
        }
    }
}

// ---------------- K6: layer-2 edge weights (edge-parallel) ----------------------
__global__ void k_w2() {
    int e = blockIdx.x * blockDim.x + threadIdx.x;
    if (e < ET) {
        int s = g_esrc[e], d = g_edst[e];
        g_w2[e] = __expf(lrelu(g_as2[s] + g_ad2[d]));
    }
}

// ---------------- K7: layer-2 GAT agg + ELU + LN -> out, + re-zero --------------
__global__ void __launch_bounds__(256) k_agg2(const float* __restrict__ b2,
                                              const float* __restrict__ g2,
                                              const float* __restrict__ bt2,
                                              float* __restrict__ out) {
    int n = blockIdx.x * 8 + (threadIdx.x >> 5);
    int lane = threadIdx.x & 31;
    int start = g_rowptr[n], end = g_rowptr[n + 1];

    float den = 0.f;
    float a0 = 0.f, a1 = 0.f, a2 = 0.f, a3 = 0.f;
#pragma unroll 4
    for (int j = start; j < end; j++) {
        int s = __ldg(&g_esrc[j]);
        float wf = __ldg(&g_w2[j]);
        den += wf;
        uint2 raw = *(const uint2*)&g_h2h[s * HID + lane * 4];
        float2 f01 = __half22float2(*(__half2*)&raw.x);
        float2 f23 = __half22float2(*(__half2*)&raw.y);
        a0 = fmaf(wf, f01.x, a0);
        a1 = fmaf(wf, f01.y, a1);
        a2 = fmaf(wf, f23.x, a2);
        a3 = fmaf(wf, f23.y, a3);
    }
    float rd = 1.0f / den;
    a0 *= rd; a1 *= rd; a2 *= rd; a3 *= rd;

    int ch = lane * 4;
    a0 += b2[ch]; a1 += b2[ch + 1]; a2 += b2[ch + 2]; a3 += b2[ch + 3];
    a0 = a0 > 0.f ? a0 : expm1f(a0);
    a1 = a1 > 0.f ? a1 : expm1f(a1);
    a2 = a2 > 0.f ? a2 : expm1f(a2);
    a3 = a3 > 0.f ? a3 : expm1f(a3);
    float s4 = a0 + a1 + a2 + a3;
#pragma unroll
    for (int off = 16; off; off >>= 1) s4 += __shfl_xor_sync(0xffffffffu, s4, off);
    float mu = s4 * (1.0f / 128.0f);
    float c0 = a0 - mu, c1 = a1 - mu, c2 = a2 - mu, c3 = a3 - mu;
    float v4 = c0 * c0 + c1 * c1 + c2 * c2 + c3 * c3;
#pragma unroll
    for (int off = 16; off; off >>= 1) v4 += __shfl_xor_sync(0xffffffffu, v4, off);
    float inv = rsqrtf(v4 * (1.0f / 128.0f) + LN_EPS);
    float4 o;
    o.x = fmaf(c0 * inv, g2[ch + 0], bt2[ch + 0]);
    o.y = fmaf(c1 * inv, g2[ch + 1], bt2[ch + 1]);
    o.z = fmaf(c2 * inv, g2[ch + 2], bt2[ch + 2]);
    o.w = fmaf(c3 * inv, g2[ch + 3], bt2[ch + 3]);
    *(float4*)&out[n * HID + ch] = o;

    // re-zero degree histogram for next graph replay
    int gi = blockIdx.x * 256 + threadIdx.x;
    if (gi < NN) g_deg[gi] = 0;
}

// ---------------- launch ----------------
extern "C" void kernel_launch(void* const* d_in, const int* in_sizes, int n_in,
                              void* d_out, int out_size) {
    const float* x     = (const float*)d_in[0];
    const int*   ei    = (const int*)d_in[1];
    const float* W1    = (const float*)d_in[2];
    const float* asr1  = (const float*)d_in[3];
    const float* adt1  = (const float*)d_in[4];
    const float* b1    = (const float*)d_in[5];
    const float* g1    = (const float*)d_in[6];
    const float* bt1   = (const float*)d_in[7];
    const float* W2    = (const float*)d_in[8];
    const float* asr2  = (const float*)d_in[9];
    const float* adt2  = (const float*)d_in[10];
    const float* b2    = (const float*)d_in[11];
    const float* g2    = (const float*)d_in[12];
    const float* bt2   = (const float*)d_in[13];
    float* out = (float*)d_out;

    const int SMEM2 = (128 * APITCH + 32 * APITCH) * sizeof(__half);  // 43.5KB
    cudaFuncSetAttribute(k_gemm2t, cudaFuncAttributeMaxDynamicSharedMemorySize, SMEM2);

    k_gemm1h<<<6250, 128>>>(x, W1, asr1, adt1, ei);
    k_scan1<<<NB, 1024>>>();
    k_scan2<<<NB, 1024>>>();
    k_scatterW<<<(ET + 255) / 256, 256>>>(ei);
    k_agg1<<<NN / 8, 256>>>(b1, g1, bt1);
    k_gemm2t<<<592, 128, SMEM2>>>(W2, asr2, adt2);
    k_w2<<<(ET + 255) / 256, 256>>>();
    k_agg2<<<NN / 8, 256>>>(b2, g2, bt2, out);
}

// round 5
// speedup vs baseline: 1.6661x; 1.0427x over previous
#include <cuda_runtime.h>
#include <cuda_fp16.h>
#include <math.h>

#define NN 100000
#define IN_CH 16
#define HID 128
#define EE 1600000
#define ET (EE + NN)
#define NB 98            // ceil(NN/1024)
#define NEG 0.2f
#define LN_EPS 1e-5f

// ---------------- scratch (static device globals; zero-init at load) ------------
__device__ __half g_h1h[NN * HID];    // layer1 features (fp16, gather target)
__device__ __half g_h2h[NN * HID];    // layer2 features (fp16, gather target)
__device__ __half g_hlnh[NN * HID];   // post ELU+LN features (fp16, gemm2 A input)
__device__ float  g_as1[NN * 4];
__device__ float  g_ad1[NN * 4];
__device__ float  g_as2[NN];
__device__ float  g_ad2[NN];
__device__ float  g_w1[ET * 4];       // layer-1 per-edge softmax numerators (CSR order)
__device__ float  g_w2[ET];           // layer-2 per-edge softmax numerators (CSR order)
__device__ int    g_deg[NN];          // zeroed by agg2 tail of previous run
__device__ int    g_scanpart[NN];
__device__ int    g_blocksum[NB];
__device__ int    g_rowptr[NN + 1];
__device__ int    g_cursor[NN];
__device__ int    g_esrc[ET];

__device__ __forceinline__ float lrelu(float e) { return e > 0.f ? e : NEG * e; }

// ---------------- mma / ldmatrix helpers ---------------------------------------
__device__ __forceinline__ void mma16816(float& d0, float& d1, float& d2, float& d3,
                                         unsigned a0, unsigned a1, unsigned a2, unsigned a3,
                                         unsigned b0, unsigned b1) {
    asm volatile(
        "mma.sync.aligned.m16n8k16.row.col.f32.f16.f16.f32 "
        "{%0,%1,%2,%3},{%4,%5,%6,%7},{%8,%9},{%0,%1,%2,%3};"
        : "+f"(d0), "+f"(d1), "+f"(d2), "+f"(d3)
        : "r"(a0), "r"(a1), "r"(a2), "r"(a3), "r"(b0), "r"(b1));
}
__device__ __forceinline__ void ldsm4(unsigned& r0, unsigned& r1, unsigned& r2, unsigned& r3,
                                      unsigned addr) {
    asm volatile("ldmatrix.sync.aligned.m8n8.x4.shared.b16 {%0,%1,%2,%3},[%4];"
                 : "=r"(r0), "=r"(r1), "=r"(r2), "=r"(r3) : "r"(addr));
}
__device__ __forceinline__ void ldsm4t(unsigned& r0, unsigned& r1, unsigned& r2, unsigned& r3,
                                       unsigned addr) {
    asm volatile("ldmatrix.sync.aligned.m8n8.x4.trans.shared.b16 {%0,%1,%2,%3},[%4];"
                 : "=r"(r0), "=r"(r1), "=r"(r2), "=r"(r3) : "r"(addr));
}

// ---------------- K0: gemm1 (16 nodes/block) + alpha dots + degree histogram ----
__global__ void __launch_bounds__(128) k_gemm1h(const float* __restrict__ x,
                                                const float* __restrict__ W1,
                                                const float* __restrict__ a_src,
                                                const float* __restrict__ a_dst,
                                                const int* __restrict__ ei) {
    __shared__ float sW1[IN_CH * HID];   // 2048
    __shared__ float spa[IN_CH * 8];     // pa[k][h][sd]
    __shared__ float sx[16 * IN_CH];     // 16 nodes of x
    int t = threadIdx.x;
    int n0 = blockIdx.x * 16;

#pragma unroll
    for (int i = 0; i < 16; i++) sW1[i * 128 + t] = W1[i * 128 + t];
    __syncthreads();
    {   // pa[k*8 + h*2 + sd] = sum_c W1[k, h*32+c] * a_{sd}[h*32+c]
        int k = t >> 3, h = (t >> 1) & 3, sd = t & 1;
        const float* av = sd ? a_dst : a_src;
        float s = 0.f;
#pragma unroll
        for (int c = 0; c < 32; c++) s = fmaf(sW1[k * 128 + h * 32 + c], av[h * 32 + c], s);
        spa[t] = s;
    }
    if (t < 64) ((float4*)sx)[t] = ((const float4*)x)[n0 * 4 + t];
    __syncthreads();

#pragma unroll 2
    for (int i = 0; i < 16; i++) {
        const float* xr = &sx[i * IN_CH];
        float acc = 0.f;
#pragma unroll
        for (int k = 0; k < IN_CH; k++) acc = fmaf(xr[k], sW1[k * 128 + t], acc);
        g_h1h[(n0 + i) * HID + t] = __float2half_rn(acc);
        if (t < 8) {
            int h = t & 3, sd = t >> 2;
            float v = 0.f;
#pragma unroll
            for (int k = 0; k < IN_CH; k++) v = fmaf(xr[k], spa[k * 8 + h * 2 + sd], v);
            if (sd == 0) g_as1[(n0 + i) * 4 + h] = v;
            else         g_ad1[(n0 + i) * 4 + h] = v;
        }
    }

    // degree histogram (grid-stride over all edges incl. self loops)
    for (int e = blockIdx.x * 128 + t; e < ET; e += 6250 * 128) {
        int d = (e < EE) ? ei[EE + e] : (e - EE);
        atomicAdd(&g_deg[d], 1);
    }
}

// ---------------- K1/K2: two-phase scan -----------------------------------------
__global__ void __launch_bounds__(1024) k_scan1() {
    __shared__ int sh[1024];
    int t = threadIdx.x;
    int i = blockIdx.x * 1024 + t;
    int v = (i < NN) ? g_deg[i] : 0;
    sh[t] = v;
    __syncthreads();
#pragma unroll
    for (int off = 1; off < 1024; off <<= 1) {
        int tv = (t >= off) ? sh[t - off] : 0;
        __syncthreads();
        sh[t] += tv;
        __syncthreads();
    }
    if (i < NN) g_scanpart[i] = sh[t] - v;  // exclusive within block
    if (t == 1023) g_blocksum[blockIdx.x] = sh[1023];
}

__global__ void __launch_bounds__(1024) k_scan2() {
    __shared__ int soff;
    int t = threadIdx.x;
    if (t == 0) {
        int s = 0;
        for (int b = 0; b < blockIdx.x; b++) s += g_blocksum[b];
        soff = s;
    }
    __syncthreads();
    int i = blockIdx.x * 1024 + t;
    if (i < NN) {
        int r = g_scanpart[i] + soff;
        g_rowptr[i] = r;
        g_cursor[i] = r;
    }
    if (i == 0) g_rowptr[NN] = ET;
}

// ---------------- K3: scatter edges into CSR (src only; dst implicit) -----------
__global__ void k_scatter(const int* __restrict__ ei) {
    int e = blockIdx.x * blockDim.x + threadIdx.x;
    if (e >= ET) return;
    int s, d;
    if (e < EE) { s = ei[e]; d = ei[EE + e]; }
    else        { s = e - EE; d = s; }
    int p = atomicAdd(&g_cursor[d], 1);
    g_esrc[p] = s;
}

// ---------------- K4: layer-1 edge weights, node-parallel (dst implicit) --------
__global__ void __launch_bounds__(256) k_w1() {
    int n = blockIdx.x * 8 + (threadIdx.x >> 5);
    int lane = threadIdx.x & 31;
    float4 ad = *(const float4*)&g_ad1[n * 4];   // broadcast per warp (same line)
    int start = g_rowptr[n], end = g_rowptr[n + 1];
    for (int j = start + lane; j < end; j += 32) {
        int s = __ldg(&g_esrc[j]);
        float4 as = *(const float4*)&g_as1[s * 4];
        float4 w;
        w.x = __expf(lrelu(as.x + ad.x));
        w.y = __expf(lrelu(as.y + ad.y));
        w.z = __expf(lrelu(as.z + ad.z));
        w.w = __expf(lrelu(as.w + ad.w));
        *(float4*)&g_w1[j * 4] = w;              // coalesced store
    }
}

// ---------------- K5: layer-1 GAT agg (precomputed weights) + ELU + LN ----------
__global__ void __launch_bounds__(256) k_agg1(const float* __restrict__ b1,
                                              const float* __restrict__ g1,
                                              const float* __restrict__ bt1) {
    int n = blockIdx.x * 8 + (threadIdx.x >> 5);
    int lane = threadIdx.x & 31;
    int h = lane >> 3;
    int start = g_rowptr[n], end = g_rowptr[n + 1];

    float den = 0.f;
    float a0 = 0.f, a1 = 0.f, a2 = 0.f, a3 = 0.f;
#pragma unroll 4
    for (int j = start; j < end; j++) {
        int s = __ldg(&g_esrc[j]);
        float wf = __ldg(&g_w1[j * 4 + h]);
        den += wf;
        uint2 raw = *(const uint2*)&g_h1h[s * HID + lane * 4];
        float2 f01 = __half22float2(*(__half2*)&raw.x);
        float2 f23 = __half22float2(*(__half2*)&raw.y);
        a0 = fmaf(wf, f01.x, a0);
        a1 = fmaf(wf, f01.y, a1);
        a2 = fmaf(wf, f23.x, a2);
        a3 = fmaf(wf, f23.y, a3);
    }
    float rd = 1.0f / den;
    a0 *= rd; a1 *= rd; a2 *= rd; a3 *= rd;

    int ch = lane * 4;
    a0 += b1[ch]; a1 += b1[ch + 1]; a2 += b1[ch + 2]; a3 += b1[ch + 3];
    a0 = a0 > 0.f ? a0 : expm1f(a0);
    a1 = a1 > 0.f ? a1 : expm1f(a1);
    a2 = a2 > 0.f ? a2 : expm1f(a2);
    a3 = a3 > 0.f ? a3 : expm1f(a3);
    float s4 = a0 + a1 + a2 + a3;
#pragma unroll
    for (int off = 16; off; off >>= 1) s4 += __shfl_xor_sync(0xffffffffu, s4, off);
    float mu = s4 * (1.0f / 128.0f);
    float c0 = a0 - mu, c1 = a1 - mu, c2 = a2 - mu, c3 = a3 - mu;
    float v4 = c0 * c0 + c1 * c1 + c2 * c2 + c3 * c3;
#pragma unroll
    for (int off = 16; off; off >>= 1) v4 += __shfl_xor_sync(0xffffffffu, v4, off);
    float inv = rsqrtf(v4 * (1.0f / 128.0f) + LN_EPS);
    float o0 = fmaf(c0 * inv, g1[ch + 0], bt1[ch + 0]);
    float o1 = fmaf(c1 * inv, g1[ch + 1], bt1[ch + 1]);
    float o2 = fmaf(c2 * inv, g1[ch + 2], bt1[ch + 2]);
    float o3 = fmaf(c3 * inv, g1[ch + 3], bt1[ch + 3]);
    __half2 p01 = __floats2half2_rn(o0, o1);
    __half2 p23 = __floats2half2_rn(o2, o3);
    uint2 st;
    st.x = *(unsigned*)&p01;
    st.y = *(unsigned*)&p23;
    *(uint2*)&g_hlnh[n * HID + ch] = st;
}

// ---------------- K6: h2 = hln @ W2 via fp16 tensor cores (+ alpha2 dots) -------
#define APITCH 136   // halves; 272B row pitch
__global__ void __launch_bounds__(128) k_gemm2t(const float* __restrict__ W2,
                                                const float* __restrict__ asw,
                                                const float* __restrict__ adw) {
    extern __shared__ __half smh[];
    __half* sW = smh;                    // [128][APITCH]
    __half* sA = smh + 128 * APITCH;     // [32][APITCH], reused as C staging
    int t = threadIdx.x;
    int w = t >> 5, lane = t & 31;
    int mrow0 = (w & 1) * 16;
    int ncol0 = (w >> 1) * 64;

    for (int i = t; i < 16384; i += 128) {
        int r = i >> 7, c = i & 127;
        sW[r * APITCH + c] = __float2half_rn(W2[i]);
    }
    unsigned swb = (unsigned)__cvta_generic_to_shared(sW);
    unsigned sab = (unsigned)__cvta_generic_to_shared(sA);
    unsigned a_off = ((unsigned)(lane & 15) * APITCH + ((lane >> 4) << 3)) * 2;
    __syncthreads();

    for (int n0 = blockIdx.x * 32; n0 < NN; n0 += 592 * 32) {
        __syncthreads();
        for (int i = t; i < 32 * 64; i += 128) {
            int r = i >> 6, c2 = i & 63;
            ((unsigned*)sA)[r * (APITCH / 2) + c2] =
                ((const unsigned*)&g_hlnh[(unsigned)(n0 + r) * HID])[c2];
        }
        __syncthreads();

        float acc[8][4];
#pragma unroll
        for (int q = 0; q < 8; q++)
#pragma unroll
            for (int r = 0; r < 4; r++) acc[q][r] = 0.f;

#pragma unroll
        for (int k0 = 0; k0 < 8; k0++) {
            unsigned a0, a1, a2, a3;
            ldsm4(a0, a1, a2, a3, sab + (unsigned)mrow0 * APITCH * 2 + (unsigned)k0 * 32 + a_off);
#pragma unroll
            for (int nt = 0; nt < 4; nt++) {
                unsigned b0, b1, b2, b3;
                unsigned baddr = swb + ((unsigned)(k0 * 16 + (lane & 15)) * APITCH
                                        + ncol0 + nt * 16 + ((lane >> 4) << 3)) * 2;
                ldsm4t(b0, b1, b2, b3, baddr);
                mma16816(acc[2 * nt][0], acc[2 * nt][1], acc[2 * nt][2], acc[2 * nt][3],
                         a0, a1, a2, a3, b0, b1);
                mma16816(acc[2 * nt + 1][0], acc[2 * nt + 1][1], acc[2 * nt + 1][2], acc[2 * nt + 1][3],
                         a0, a1, a2, a3, b2, b3);
            }
        }
        __syncthreads();

#pragma unroll
        for (int nt = 0; nt < 8; nt++) {
            int n = ncol0 + nt * 8 + 2 * (lane & 3);
            int r = mrow0 + (lane >> 2);
            __half2 lo = __floats2half2_rn(acc[nt][0], acc[nt][1]);
            __half2 hi = __floats2half2_rn(acc[nt][2], acc[nt][3]);
            *(__half2*)&sA[r * APITCH + n] = lo;
            *(__half2*)&sA[(r + 8) * APITCH + n] = hi;
        }
        __syncthreads();

        for (int i = t; i < 32 * 64; i += 128) {
            int r = i >> 6, c2 = i & 63;
            ((unsigned*)&g_h2h[(unsigned)(n0 + r) * HID])[c2] =
                ((unsigned*)sA)[r * (APITCH / 2) + c2];
        }
        if (t < 32) {
            float ps = 0.f, pd = 0.f;
#pragma unroll 4
            for (int c = 0; c < 128; c += 2) {
                float2 f = __half22float2(*(__half2*)&sA[t * APITCH + c]);
                ps = fmaf(f.x, __ldg(&asw[c]), fmaf(f.y, __ldg(&asw[c + 1]), ps));
                pd = fmaf(f.x, __ldg(&adw[c]), fmaf(f.y, __ldg(&adw[c + 1]), pd));
            }
            g_as2[n0 + t] = ps;
            g_ad2[n0 + t] = pd;
        }
    }
}

// ---------------- K7: layer-2 edge weights, node-parallel (dst implicit) --------
__global__ void __launch_bounds__(256) k_w2() {
    int n = blockIdx.x * 8 + (threadIdx.x >> 5);
    int lane = threadIdx.x & 31;
    float adn = g_ad2[n];
    int start = g_rowptr[n], end = g_rowptr[n + 1];
    for (int j = start + lane; j < end; j += 32) {
        int s = __ldg(&g_esrc[j]);
        g_w2[j] = __expf(lrelu(__ldg(&g_as2[s]) + adn));
    }
}

// ---------------- K8: layer-2 GAT agg + ELU + LN -> out, + re-zero --------------
__global__ void __launch_bounds__(256) k_agg2(const float* __restrict__ b2,
                                              const float* __restrict__ g2,
                                              const float* __restrict__ bt2,
                                              float* __restrict__ out) {
    int n = blockIdx.x * 8 + (threadIdx.x >> 5);
    int lane = threadIdx.x & 31;
    int start = g_rowptr[n], end = g_rowptr[n + 1];

    float den = 0.f;
    float a0 = 0.f, a1 = 0.f, a2 = 0.f, a3 = 0.f;
#pragma unroll 4
    for (int j = start; j < end; j++) {
        int s = __ldg(&g_esrc[j]);
        float wf = __ldg(&g_w2[j]);
        den += wf;
        uint2 raw = *(const uint2*)&g_h2h[s * HID + lane * 4];
        float2 f01 = __half22float2(*(__half2*)&raw.x);
        float2 f23 = __half22float2(*(__half2*)&raw.y);
        a0 = fmaf(wf, f01.x, a0);
        a1 = fmaf(wf, f01.y, a1);
        a2 = fmaf(wf, f23.x, a2);
        a3 = fmaf(wf, f23.y, a3);
    }
    float rd = 1.0f / den;
    a0 *= rd; a1 *= rd; a2 *= rd; a3 *= rd;

    int ch = lane * 4;
    a0 += b2[ch]; a1 += b2[ch + 1]; a2 += b2[ch + 2]; a3 += b2[ch + 3];
    a0 = a0 > 0.f ? a0 : expm1f(a0);
    a1 = a1 > 0.f ? a1 : expm1f(a1);
    a2 = a2 > 0.f ? a2 : expm1f(a2);
    a3 = a3 > 0.f ? a3 : expm1f(a3);
    float s4 = a0 + a1 + a2 + a3;
#pragma unroll
    for (int off = 16; off; off >>= 1) s4 += __shfl_xor_sync(0xffffffffu, s4, off);
    float mu = s4 * (1.0f / 128.0f);
    float c0 = a0 - mu, c1 = a1 - mu, c2 = a2 - mu, c3 = a3 - mu;
    float v4 = c0 * c0 + c1 * c1 + c2 * c2 + c3 * c3;
#pragma unroll
    for (int off = 16; off; off >>= 1) v4 += __shfl_xor_sync(0xffffffffu, v4, off);
    float inv = rsqrtf(v4 * (1.0f / 128.0f) + LN_EPS);
    float4 o;
    o.x = fmaf(c0 * inv, g2[ch + 0], bt2[ch + 0]);
    o.y = fmaf(c1 * inv, g2[ch + 1], bt2[ch + 1]);
    o.z = fmaf(c2 * inv, g2[ch + 2], bt2[ch + 2]);
    o.w = fmaf(c3 * inv, g2[ch + 3], bt2[ch + 3]);
    *(float4*)&out[n * HID + ch] = o;

    // re-zero degree histogram for next graph replay
    int gi = blockIdx.x * 256 + threadIdx.x;
    if (gi < NN) g_deg[gi] = 0;
}

// ---------------- launch ----------------
extern "C" void kernel_launch(void* const* d_in, const int* in_sizes, int n_in,
                              void* d_out, int out_size) {
    const float* x     = (const float*)d_in[0];
    const int*   ei    = (const int*)d_in[1];
    const float* W1    = (const float*)d_in[2];
    const float* asr1  = (const float*)d_in[3];
    const float* adt1  = (const float*)d_in[4];
    const float* b1    = (const float*)d_in[5];
    const float* g1    = (const float*)d_in[6];
    const float* bt1   = (const float*)d_in[7];
    const float* W2    = (const float*)d_in[8];
    const float* asr2  = (const float*)d_in[9];
    const float* adt2  = (const float*)d_in[10];
    const float* b2    = (const float*)d_in[11];
    const float* g2    = (const float*)d_in[12];
    const float* bt2   = (const float*)d_in[13];
    float* out = (float*)d_out;

    const int SMEM2 = (128 * APITCH + 32 * APITCH) * sizeof(__half);  // 43.5KB
    cudaFuncSetAttribute(k_gemm2t, cudaFuncAttributeMaxDynamicSharedMemorySize, SMEM2);

    k_gemm1h<<<6250, 128>>>(x, W1, asr1, adt1, ei);
    k_scan1<<<NB, 1024>>>();
    k_scan2<<<NB, 1024>>>();
    k_scatter<<<(ET + 255) / 256, 256>>>(ei);
    k_w1<<<NN / 8, 256>>>();
    k_agg1<<<NN / 8, 256>>>(b1, g1, bt1);
    k_gemm2t<<<592, 128, SMEM2>>>(W2, asr2, adt2);
    k_w2<<<NN / 8, 256>>>();
    k_agg2<<<NN / 8, 256>>>(b2, g2, bt2, out);
}